// round 1
// baseline (speedup 1.0000x reference)
#include <cuda_runtime.h>
#include <cuda_bf16.h>

// DeepSeek-V3 top-k router: T=131072 tokens, 256 experts, 8 groups of 32,
// top-4 groups by (top-2 sum), then top-8 experts, sigmoid-score weights
// normalized and scaled by 2.5.
//
// Layout: one warp per token. Lane l owns expert g*32+l for each group g.
// Output: d_out[0..T*8)        = topk indices (stored as float)
//         d_out[T*8..2*T*8)    = topk weights

static __device__ __forceinline__ float sigmoidf_fast(float x) {
    return __fdividef(1.0f, 1.0f + __expf(-x));
}

__global__ __launch_bounds__(256, 1) void deepseek_router_kernel(
    const float* __restrict__ logits,
    const float* __restrict__ bias,
    float* __restrict__ out_idx,   // T*8 floats
    float* __restrict__ out_w,     // T*8 floats
    int T)
{
    const unsigned FULL = 0xffffffffu;
    int warp = (int)((blockIdx.x * blockDim.x + threadIdx.x) >> 5);
    int lane = threadIdx.x & 31;
    if (warp >= T) return;

    const float* row = logits + (long long)warp * 256;

    float s[8];      // sigmoid scores (for weights)
    float cand[8];   // corrected scores (for selection), later masked
    float gs[8];     // group scores (uniform across lanes)

    #pragma unroll
    for (int g = 0; g < 8; g++) {
        float x = row[g * 32 + lane];
        float sv = sigmoidf_fast(x);
        s[g] = sv;
        cand[g] = sv + __ldg(bias + g * 32 + lane);
    }

    // ---- group score = sum of top-2 corrected scores within each 32-wide group
    #pragma unroll
    for (int g = 0; g < 8; g++) {
        float m1 = cand[g], m2 = -1e30f;
        #pragma unroll
        for (int off = 16; off > 0; off >>= 1) {
            float o1 = __shfl_xor_sync(FULL, m1, off);
            float o2 = __shfl_xor_sync(FULL, m2, off);
            float hi = fmaxf(m1, o1);
            float lo = fminf(m1, o1);
            m2 = fmaxf(fmaxf(m2, o2), lo);
            m1 = hi;
        }
        gs[g] = m1 + m2;   // identical on all lanes (multiset top-2 is order-free)
    }

    // ---- top-4 groups (computed redundantly & identically on every lane)
    unsigned selmask = 0;
    #pragma unroll
    for (int k = 0; k < 4; k++) {
        float best = -1e30f; int bg = 0;
        #pragma unroll
        for (int g = 0; g < 8; g++) {
            bool better = (((selmask >> g) & 1u) == 0u) && (gs[g] > best);
            best = better ? gs[g] : best;
            bg   = better ? g : bg;
        }
        selmask |= (1u << bg);
    }

    // ---- mask: unselected groups become exactly 0.0 (matches jnp.where)
    #pragma unroll
    for (int g = 0; g < 8; g++) {
        cand[g] = ((selmask >> g) & 1u) ? cand[g] : 0.0f;
    }

    // ---- iterative top-8 extraction over all 256 (value desc, index asc)
    float ti[8], tw[8];
    float wsum = 0.0f;
    #pragma unroll
    for (int k = 0; k < 8; k++) {
        // local argmax over this lane's 8 candidates (earlier g wins ties)
        float bv = cand[0]; int bi = lane;  // expert idx of g=0 is 0*32+lane
        #pragma unroll
        for (int g = 1; g < 8; g++) {
            bool better = cand[g] > bv;
            bv = better ? cand[g] : bv;
            bi = better ? g * 32 + lane : bi;
        }
        // warp argmax; tiebreak = smaller expert index (lax.top_k stability)
        #pragma unroll
        for (int off = 16; off > 0; off >>= 1) {
            float ov = __shfl_xor_sync(FULL, bv, off);
            int   oi = __shfl_xor_sync(FULL, bi, off);
            bool better = (ov > bv) || (ov == bv && oi < bi);
            bv = better ? ov : bv;
            bi = better ? oi : bi;
        }
        // (bv, bi) now identical on all lanes: total order on (value, -idx)
        int bg2 = bi >> 5;
        float sv = 0.0f;
        #pragma unroll
        for (int g = 0; g < 8; g++) if (g == bg2) sv = s[g];   // static unroll, no spill
        float w = __shfl_sync(FULL, sv, bi & 31);
        if ((bi & 31) == lane) {
            #pragma unroll
            for (int g = 0; g < 8; g++) if (g == bg2) cand[g] = -1e30f;
        }
        ti[k] = (float)bi;
        tw[k] = w;
        wsum += w;
    }

    float inv = 2.5f * __fdividef(1.0f, wsum + 1e-20f);

    if (lane == 0) {
        float4* oi4 = (float4*)(out_idx + (long long)warp * 8);
        float4* ow4 = (float4*)(out_w   + (long long)warp * 8);
        oi4[0] = make_float4(ti[0], ti[1], ti[2], ti[3]);
        oi4[1] = make_float4(ti[4], ti[5], ti[6], ti[7]);
        ow4[0] = make_float4(tw[0] * inv, tw[1] * inv, tw[2] * inv, tw[3] * inv);
        ow4[1] = make_float4(tw[4] * inv, tw[5] * inv, tw[6] * inv, tw[7] * inv);
    }
}

extern "C" void kernel_launch(void* const* d_in, const int* in_sizes, int n_in,
                              void* d_out, int out_size)
{
    const float* logits = (const float*)d_in[0];
    const float* bias   = (const float*)d_in[1];
    int T = in_sizes[0] / 256;

    float* out    = (float*)d_out;
    float* out_idx = out;
    float* out_w   = out + (long long)T * 8;

    const int WARPS_PER_BLOCK = 8;
    dim3 block(WARPS_PER_BLOCK * 32);
    dim3 grid((T + WARPS_PER_BLOCK - 1) / WARPS_PER_BLOCK);
    deepseek_router_kernel<<<grid, block>>>(logits, bias, out_idx, out_w, T);
}

// round 2
// speedup vs baseline: 1.5979x; 1.5979x over previous
#include <cuda_runtime.h>
#include <cuda_bf16.h>

// DeepSeek-V3 top-k router, REDUX.SYNC-based selection.
// One warp per token; lane l owns expert g*32+l for group g.
// Keys are order-preserving uint transforms of corrected scores, so all
// selection comparisons are exact (bit-identical ordering to float compare).
// Output: d_out[0..T*8) = indices (float), d_out[T*8..2*T*8) = weights.

static __device__ __forceinline__ unsigned redux_max_u32(unsigned x) {
    unsigned r;
    asm volatile("redux.sync.max.u32 %0, %1, 0xffffffff;" : "=r"(r) : "r"(x));
    return r;
}

// order-preserving float->uint (exact total order, bijective)
static __device__ __forceinline__ unsigned f2ou(float f) {
    unsigned u = __float_as_uint(f);
    return u ^ ((unsigned)((int)u >> 31) | 0x80000000u);
}
static __device__ __forceinline__ float ou2f(unsigned k) {
    unsigned m = (unsigned)((int)k >> 31);          // all-ones if msb set
    return __uint_as_float(k ^ ((m & 0x80000000u) | ~m));
}

__global__ __launch_bounds__(256) void deepseek_router_kernel(
    const float* __restrict__ logits,
    const float* __restrict__ bias,
    float* __restrict__ out_idx,
    float* __restrict__ out_w,
    int T)
{
    const unsigned FULL = 0xffffffffu;
    int warp = (int)((blockIdx.x * blockDim.x + threadIdx.x) >> 5);
    int lane = threadIdx.x & 31;
    if (warp >= T) return;

    const float* row = logits + (long long)warp * 256;

    unsigned key[8];   // corrected scores in order-preserving uint domain
    float gs[8];       // group scores (uniform across lanes)

    #pragma unroll
    for (int g = 0; g < 8; g++) {
        float x = row[g * 32 + lane];
        float sv = __fdividef(1.0f, 1.0f + __expf(-x));
        float c = sv + __ldg(bias + g * 32 + lane);
        key[g] = f2ou(c);
    }

    // ---- group score = top-2 sum via two warp redux per group
    #pragma unroll
    for (int g = 0; g < 8; g++) {
        unsigned m1 = redux_max_u32(key[g]);
        unsigned t  = (key[g] == m1) ? 0u : key[g];   // drop max instance(s)
        unsigned m2 = redux_max_u32(t);
        gs[g] = ou2f(m1) + ou2f(m2);
    }

    // ---- rank groups pairwise; selected = rank < 4 (ties favor lower index)
    int rank[8] = {0, 0, 0, 0, 0, 0, 0, 0};
    #pragma unroll
    for (int g = 1; g < 8; g++) {
        #pragma unroll
        for (int h = 0; h < g; h++) {
            if (gs[h] >= gs[g]) rank[g]++; else rank[h]++;
        }
    }
    #pragma unroll
    for (int g = 0; g < 8; g++) {
        if (rank[g] >= 4) key[g] = 0u;   // 0 = smaller than any real key
    }

    // ---- iterative top-8: local IMNMX max + one redux per pick
    float ti[8], tw[8];
    float wsum = 0.0f;
    #pragma unroll
    for (int k = 0; k < 8; k++) {
        unsigned lm = key[0];
        #pragma unroll
        for (int g = 1; g < 8; g++) lm = max(lm, key[g]);
        unsigned win = redux_max_u32(lm);

        // locate winner slot in this lane (descending g => smallest g on dup)
        int gsel = 0;
        #pragma unroll
        for (int g = 7; g >= 0; g--) {
            if (key[g] == win) gsel = g + 1;
        }
        unsigned bm = __ballot_sync(FULL, gsel != 0);
        int src = __ffs((int)bm) - 1;                 // lowest matching lane
        int gw  = __shfl_sync(FULL, gsel, src) - 1;
        int bi  = gw * 32 + src;                      // expert index (uniform)

        // clear exactly one instance (the one on lane src at its gsel slot)
        bool amsrc = (lane == src);
        #pragma unroll
        for (int g = 0; g < 8; g++) {
            if (amsrc && (gsel == g + 1)) key[g] = 0u;
        }

        // weight = sigmoid score = corrected - bias   (exact to ~1 ulp)
        float w = ou2f(win) - __ldg(bias + bi);
        ti[k] = (float)bi;
        tw[k] = w;
        wsum += w;
    }

    float inv = 2.5f * __fdividef(1.0f, wsum + 1e-20f);

    if (lane == 0) {
        float4* oi4 = (float4*)(out_idx + (long long)warp * 8);
        float4* ow4 = (float4*)(out_w   + (long long)warp * 8);
        oi4[0] = make_float4(ti[0], ti[1], ti[2], ti[3]);
        oi4[1] = make_float4(ti[4], ti[5], ti[6], ti[7]);
        ow4[0] = make_float4(tw[0] * inv, tw[1] * inv, tw[2] * inv, tw[3] * inv);
        ow4[1] = make_float4(tw[4] * inv, tw[5] * inv, tw[6] * inv, tw[7] * inv);
    }
}

extern "C" void kernel_launch(void* const* d_in, const int* in_sizes, int n_in,
                              void* d_out, int out_size)
{
    const float* logits = (const float*)d_in[0];
    const float* bias   = (const float*)d_in[1];
    int T = in_sizes[0] / 256;

    float* out     = (float*)d_out;
    float* out_idx = out;
    float* out_w   = out + (long long)T * 8;

    const int WARPS_PER_BLOCK = 8;
    dim3 block(WARPS_PER_BLOCK * 32);
    dim3 grid((T + WARPS_PER_BLOCK - 1) / WARPS_PER_BLOCK);
    deepseek_router_kernel<<<grid, block>>>(logits, bias, out_idx, out_w, T);
}

// round 3
// speedup vs baseline: 1.8418x; 1.1526x over previous
#include <cuda_runtime.h>

// DeepSeek-V3 top-k router. One warp per token.
// Contiguous layout: lane l owns experts 8l..8l+7; group g = lanes 4g..4g+3.
// All selection math in float domain; order-preserving uint transform applied
// only to the per-lane max for the warp-wide __reduce_max_sync.
// Output: d_out[0..T*8) = indices (float), d_out[T*8..2*T*8) = weights.

#define FULLM 0xffffffffu

static __device__ __forceinline__ unsigned f2ou(float f) {
    unsigned u = __float_as_uint(f);
    return u ^ ((unsigned)((int)u >> 31) | 0x80000000u);
}
static __device__ __forceinline__ float ou2f(unsigned k) {
    unsigned m = (unsigned)((int)k >> 31);
    return __uint_as_float(k ^ ((m & 0x80000000u) | ~m));
}
static __device__ __forceinline__ float sigf(float x) {
    return __fdividef(1.0f, 1.0f + __expf(-x));
}

__global__ __launch_bounds__(256) void deepseek_router_kernel(
    const float* __restrict__ logits,
    const float* __restrict__ bias,
    float* __restrict__ out_idx,
    float* __restrict__ out_w,
    int T)
{
    int warp = (int)((blockIdx.x * blockDim.x + threadIdx.x) >> 5);
    int lane = threadIdx.x & 31;
    if (warp >= T) return;

    const float4* row4 = (const float4*)(logits + (long long)warp * 256);
    float4 xa = __ldg(row4 + lane * 2);
    float4 xb = __ldg(row4 + lane * 2 + 1);
    const float4* b4 = (const float4*)bias;
    float4 ba = __ldg(b4 + lane * 2);
    float4 bb = __ldg(b4 + lane * 2 + 1);

    // corrected scores for this lane's 8 consecutive experts
    float c[8];
    c[0] = sigf(xa.x) + ba.x;  c[1] = sigf(xa.y) + ba.y;
    c[2] = sigf(xa.z) + ba.z;  c[3] = sigf(xa.w) + ba.w;
    c[4] = sigf(xb.x) + bb.x;  c[5] = sigf(xb.y) + bb.y;
    c[6] = sigf(xb.z) + bb.z;  c[7] = sigf(xb.w) + bb.w;

    // ---- lane-local top-2 (exact, duplicate-preserving)
    float m1 = fmaxf(c[0], c[1]);
    float m2 = fminf(c[0], c[1]);
    #pragma unroll
    for (int i = 2; i < 8; i++) {
        float hi = fmaxf(m1, c[i]);
        m2 = fmaxf(m2, fminf(m1, c[i]));
        m1 = hi;
    }
    // ---- merge top-2 across the 4 lanes of this group (quad butterfly)
    #pragma unroll
    for (int d = 1; d <= 2; d <<= 1) {
        float o1 = __shfl_xor_sync(FULLM, m1, d);
        float o2 = __shfl_xor_sync(FULLM, m2, d);
        m2 = fmaxf(fmaxf(m2, o2), fminf(m1, o1));
        m1 = fmaxf(m1, o1);
    }
    float gs = m1 + m2;   // this lane's group score (replicated within quad)

    // ---- rank my group among the 8 (shfl pairwise, exact lower-index ties)
    int grp = lane >> 2;
    int rank = 0;
    #pragma unroll
    for (int e = 1; e < 8; e++) {
        float yo = __shfl_xor_sync(FULLM, gs, e * 4);
        int hbe = (e >= 4) ? 4 : ((e >= 2) ? 2 : 1);  // highest bit of e
        bool lowp = (grp & hbe) != 0;                 // other group index < mine
        if (yo > gs || (yo == gs && lowp)) rank++;
    }
    bool sel = rank < 4;

    // ---- mask: unselected groups become exactly 0.0 (matches jnp.where)
    #pragma unroll
    for (int i = 0; i < 8; i++) c[i] = sel ? c[i] : 0.0f;

    // ---- iterative top-8 (value desc, expert-index asc — lane-major exact)
    unsigned tpack0 = 0, tpack1 = 0;
    float tw[8];
    float wsum = 0.0f;
    #pragma unroll
    for (int k = 0; k < 8; k++) {
        float lm = c[0];
        #pragma unroll
        for (int i = 1; i < 8; i++) lm = fmaxf(lm, c[i]);
        unsigned lmu  = f2ou(lm);
        unsigned winu = __reduce_max_sync(FULLM, lmu);
        unsigned bal  = __ballot_sync(FULLM, lmu == winu);
        int src = __ffs((int)bal) - 1;        // lowest lane = lowest expert base
        bool amsrc = (lane == src);
        float win = ou2f(winu);

        int slot = 0;
        #pragma unroll
        for (int i = 7; i >= 0; i--) {
            if (amsrc && c[i] == win) slot = i;   // lowest matching slot
        }
        #pragma unroll
        for (int i = 0; i < 8; i++) {
            if (amsrc && c[i] == win) c[i] = -3.0e38f;
        }
        int sl = __shfl_sync(FULLM, slot, src);
        int bi = src * 8 + sl;                    // expert index (uniform)

        float w = win - __ldg(bias + bi);         // sigmoid score (±1 ulp)
        if (k < 4) tpack0 |= (unsigned)bi << (k * 8);
        else       tpack1 |= (unsigned)bi << ((k - 4) * 8);
        tw[k] = w;
        wsum += w;
    }

    float inv = 2.5f * __fdividef(1.0f, wsum + 1e-20f);

    if (lane == 0) {
        long long base = (long long)warp * 8;
        float4* oi4 = (float4*)(out_idx + base);
        float4* ow4 = (float4*)(out_w   + base);
        oi4[0] = make_float4((float)(tpack0 & 255), (float)((tpack0 >> 8) & 255),
                             (float)((tpack0 >> 16) & 255), (float)(tpack0 >> 24));
        oi4[1] = make_float4((float)(tpack1 & 255), (float)((tpack1 >> 8) & 255),
                             (float)((tpack1 >> 16) & 255), (float)(tpack1 >> 24));
        ow4[0] = make_float4(tw[0] * inv, tw[1] * inv, tw[2] * inv, tw[3] * inv);
        ow4[1] = make_float4(tw[4] * inv, tw[5] * inv, tw[6] * inv, tw[7] * inv);
    }
}

extern "C" void kernel_launch(void* const* d_in, const int* in_sizes, int n_in,
                              void* d_out, int out_size)
{
    const float* logits = (const float*)d_in[0];
    const float* bias   = (const float*)d_in[1];
    int T = in_sizes[0] / 256;

    float* out     = (float*)d_out;
    float* out_idx = out;
    float* out_w   = out + (long long)T * 8;

    const int WARPS_PER_BLOCK = 8;
    dim3 block(WARPS_PER_BLOCK * 32);
    dim3 grid((T + WARPS_PER_BLOCK - 1) / WARPS_PER_BLOCK);
    deepseek_router_kernel<<<grid, block>>>(logits, bias, out_idx, out_w, T);
}

// round 6
// speedup vs baseline: 2.3467x; 1.2741x over previous
#include <cuda_runtime.h>

// DeepSeek-V3 top-k router. One warp per token.
// Lane l owns experts 8l..8l+7 (group g = lanes 4g..4g+3).
// After top-4 group selection, the 128 live candidates are compacted onto all
// 32 lanes (4 each) so the top-8 extraction loop touches no dead slots.
// Output: d_out[0..T*8) = indices (float), d_out[T*8..2*T*8) = weights.

#define FULLM 0xffffffffu

static __device__ __forceinline__ unsigned f2ou(float f) {
    unsigned u = __float_as_uint(f);
    return u ^ ((unsigned)((int)u >> 31) | 0x80000000u);
}
static __device__ __forceinline__ float ou2f(unsigned k) {
    unsigned m = (unsigned)((int)k >> 31);
    return __uint_as_float(k ^ ((m & 0x80000000u) | ~m));
}
static __device__ __forceinline__ float sigf(float x) {
    return __fdividef(1.0f, 1.0f + __expf(-x));
}

__global__ __launch_bounds__(256) void deepseek_router_kernel(
    const float* __restrict__ logits,
    const float* __restrict__ bias,
    float* __restrict__ out_idx,
    float* __restrict__ out_w,
    int T)
{
    int warp = (int)((blockIdx.x * blockDim.x + threadIdx.x) >> 5);
    int lane = threadIdx.x & 31;
    if (warp >= T) return;

    const float4* row4 = (const float4*)(logits + (long long)warp * 256);
    float4 xa = __ldg(row4 + lane * 2);
    float4 xb = __ldg(row4 + lane * 2 + 1);
    const float4* b4 = (const float4*)bias;
    float4 ba = __ldg(b4 + lane * 2);
    float4 bb = __ldg(b4 + lane * 2 + 1);

    // corrected scores for this lane's 8 consecutive experts
    float c[8];
    c[0] = sigf(xa.x) + ba.x;  c[1] = sigf(xa.y) + ba.y;
    c[2] = sigf(xa.z) + ba.z;  c[3] = sigf(xa.w) + ba.w;
    c[4] = sigf(xb.x) + bb.x;  c[5] = sigf(xb.y) + bb.y;
    c[6] = sigf(xb.z) + bb.z;  c[7] = sigf(xb.w) + bb.w;

    // ---- lane-local top-2 (exact, duplicate-preserving)
    float m1 = fmaxf(c[0], c[1]);
    float m2 = fminf(c[0], c[1]);
    #pragma unroll
    for (int i = 2; i < 8; i++) {
        float hi = fmaxf(m1, c[i]);
        m2 = fmaxf(m2, fminf(m1, c[i]));
        m1 = hi;
    }
    // ---- merge top-2 across the 4 lanes of this group (quad butterfly)
    #pragma unroll
    for (int d = 1; d <= 2; d <<= 1) {
        float o1 = __shfl_xor_sync(FULLM, m1, d);
        float o2 = __shfl_xor_sync(FULLM, m2, d);
        m2 = fmaxf(fmaxf(m2, o2), fminf(m1, o1));
        m1 = fmaxf(m1, o1);
    }
    float gs = m1 + m2;   // group score (replicated within quad)

    // ---- rank my group among the 8 (pairwise shfl, exact lower-index ties)
    int grp = lane >> 2;
    int rank = 0;
    #pragma unroll
    for (int e = 1; e < 8; e++) {
        float yo = __shfl_xor_sync(FULLM, gs, e * 4);
        int hbe = (e >= 4) ? 4 : ((e >= 2) ? 2 : 1);
        bool lowp = (grp & hbe) != 0;          // other group's index < mine
        if (yo > gs || (yo == gs && lowp)) rank++;
    }
    bool sel = rank < 4;

    // ---- compact: 16 active lanes x 8 -> 32 lanes x 4, expert-order preserving
    unsigned am = __ballot_sync(FULLM, sel);          // exactly 16 bits set
    int src = (int)__fns(am, 0, (lane >> 1) + 1);     // my source (active) lane
    float rA[4], rB[4];
    #pragma unroll
    for (int i = 0; i < 4; i++) {
        rA[i] = __shfl_sync(FULLM, c[i],     src);    // source's lower half
        rB[i] = __shfl_sync(FULLM, c[4 + i], src);    // source's upper half
    }
    bool odd = (lane & 1);
    float cv[4];
    #pragma unroll
    for (int i = 0; i < 4; i++) cv[i] = odd ? rB[i] : rA[i];
    int ebase = src * 8 + (odd ? 4 : 0);              // expert index of cv[0]

    // ---- iterative top-8 over the 128 live candidates
    unsigned tpack0 = 0, tpack1 = 0;
    float tw[8];
    float wsum = 0.0f;
    #pragma unroll
    for (int k = 0; k < 8; k++) {
        float lm = fmaxf(fmaxf(cv[0], cv[1]), fmaxf(cv[2], cv[3]));
        unsigned lmu  = f2ou(lm);
        unsigned winu = __reduce_max_sync(FULLM, lmu);
        unsigned bal  = __ballot_sync(FULLM, lmu == winu);
        int wl = __ffs((int)bal) - 1;          // lowest lane = lowest expert base
        bool amw = (lane == wl);
        float win = ou2f(winu);

        // my lowest matching slot (meaningful only on winner lane)
        int slot = 0;
        #pragma unroll
        for (int i = 3; i >= 0; i--) if (cv[i] == win) slot = i;
        // clear winner's matching slot(s)
        #pragma unroll
        for (int i = 0; i < 4; i++) if (amw && cv[i] == win) cv[i] = -3.0e38f;

        int myidx = ebase + slot;
        int bi = __shfl_sync(FULLM, myidx, wl);       // winning expert (uniform)

        float w = win - __ldg(bias + bi);             // sigmoid score (+-1 ulp)
        if (k < 4) tpack0 |= (unsigned)bi << (k * 8);
        else       tpack1 |= (unsigned)bi << ((k - 4) * 8);
        tw[k] = w;
        wsum += w;
    }

    float inv = 2.5f * __fdividef(1.0f, wsum + 1e-20f);

    if (lane == 0) {
        long long base = (long long)warp * 8;
        float4* oi4 = (float4*)(out_idx + base);
        float4* ow4 = (float4*)(out_w   + base);
        oi4[0] = make_float4((float)(tpack0 & 255), (float)((tpack0 >> 8) & 255),
                             (float)((tpack0 >> 16) & 255), (float)(tpack0 >> 24));
        oi4[1] = make_float4((float)(tpack1 & 255), (float)((tpack1 >> 8) & 255),
                             (float)((tpack1 >> 16) & 255), (float)(tpack1 >> 24));
        ow4[0] = make_float4(tw[0] * inv, tw[1] * inv, tw[2] * inv, tw[3] * inv);
        ow4[1] = make_float4(tw[4] * inv, tw[5] * inv, tw[6] * inv, tw[7] * inv);
    }
}

extern "C" void kernel_launch(void* const* d_in, const int* in_sizes, int n_in,
                              void* d_out, int out_size)
{
    const float* logits = (const float*)d_in[0];
    const float* bias   = (const float*)d_in[1];
    int T = in_sizes[0] / 256;

    float* out     = (float*)d_out;
    float* out_idx = out;
    float* out_w   = out + (long long)T * 8;

    const int WARPS_PER_BLOCK = 8;
    dim3 block(WARPS_PER_BLOCK * 32);
    dim3 grid((T + WARPS_PER_BLOCK - 1) / WARPS_PER_BLOCK);
    deepseek_router_kernel<<<grid, block>>>(logits, bias, out_idx, out_w, T);
}

// round 8
// speedup vs baseline: 2.5550x; 1.0888x over previous
#include <cuda_runtime.h>

// DeepSeek-V3 top-k router. TWO tokens per warp (one per 16-lane half).
// Within a half: lane hl owns experts 16*hl..16*hl+15; group g = lane pair
// {2g, 2g+1}. After top-4 group selection the 128 live candidates are
// compacted to 8 per lane; top-8 extracted with segmented (16-lane) redux.
// Output: d_out[0..T*8) = indices (float), d_out[T*8..2*T*8) = weights.

#define FULLM 0xffffffffu

static __device__ __forceinline__ unsigned f2ou(float f) {
    unsigned u = __float_as_uint(f);
    return u ^ ((unsigned)((int)u >> 31) | 0x80000000u);
}
static __device__ __forceinline__ float ou2f(unsigned k) {
    unsigned m = (unsigned)((int)k >> 31);
    return __uint_as_float(k ^ ((m & 0x80000000u) | ~m));
}
static __device__ __forceinline__ float sigf(float x) {
    return __fdividef(1.0f, 1.0f + __expf(-x));
}

__global__ __launch_bounds__(256) void deepseek_router_kernel(
    const float* __restrict__ logits,
    const float* __restrict__ bias,
    float* __restrict__ out_idx,
    float* __restrict__ out_w,
    int T)
{
    int warp = (int)((blockIdx.x * blockDim.x + threadIdx.x) >> 5);
    int lane = threadIdx.x & 31;
    int half = lane >> 4;            // 0 or 1: which token of this warp
    int hl   = lane & 15;            // lane within my half
    unsigned halfmask = 0xffffu << (half * 16);

    int token = warp * 2 + half;
    if (token >= T) token = T - 1;   // tail safety (duplicate compute, same writes)

    // ---- load 16 experts per lane, compute corrected scores
    const float4* row4 = (const float4*)(logits + (long long)token * 256);
    const float4* b4   = (const float4*)bias;
    float c[16];
    #pragma unroll
    for (int j = 0; j < 4; j++) {
        float4 x = __ldg(row4 + hl * 4 + j);
        float4 b = __ldg(b4   + hl * 4 + j);
        c[j * 4 + 0] = sigf(x.x) + b.x;
        c[j * 4 + 1] = sigf(x.y) + b.y;
        c[j * 4 + 2] = sigf(x.z) + b.z;
        c[j * 4 + 3] = sigf(x.w) + b.w;
    }

    // ---- lane-local top-2 over 16 (exact, duplicate-preserving)
    float m1 = fmaxf(c[0], c[1]);
    float m2 = fminf(c[0], c[1]);
    #pragma unroll
    for (int i = 2; i < 16; i++) {
        float hi = fmaxf(m1, c[i]);
        m2 = fmaxf(m2, fminf(m1, c[i]));
        m1 = hi;
    }
    // ---- merge top-2 across the lane pair (group = 2 lanes)
    {
        float o1 = __shfl_xor_sync(FULLM, m1, 1);
        float o2 = __shfl_xor_sync(FULLM, m2, 1);
        m2 = fmaxf(fmaxf(m2, o2), fminf(m1, o1));
        m1 = fmaxf(m1, o1);
    }
    float gs = m1 + m2;              // group score (replicated in lane pair)

    // ---- rank my group among 8 (pairwise, exact lower-index tie rule)
    int grp = hl >> 1;
    int rank = 0;
    #pragma unroll
    for (int e = 1; e < 8; e++) {
        float yo = __shfl_xor_sync(FULLM, gs, e * 2);   // stride <=14: stays in half
        int hbe = (e >= 4) ? 4 : ((e >= 2) ? 2 : 1);
        bool lowp = (grp & hbe) != 0;                   // other group's index < mine
        if (yo > gs || (yo == gs && lowp)) rank++;
    }
    bool sel = rank < 4;

    // ---- compact: 8 active lanes x16 -> 16 lanes x8 (expert order preserved)
    unsigned am = __ballot_sync(FULLM, sel);
    unsigned hm = (am >> (half * 16)) & 0xffffu;        // 8 bits set
    int srcl = (int)__fns(hm, 0, (hl >> 1) + 1);        // local active lane
    int src  = srcl + half * 16;                        // global source lane
    bool odd = (hl & 1);
    float cv[8];
    #pragma unroll
    for (int i = 0; i < 8; i++) {
        float rA = __shfl_sync(FULLM, c[i],     src);
        float rB = __shfl_sync(FULLM, c[8 + i], src);
        cv[i] = odd ? rB : rA;
    }
    int ebase = srcl * 16 + (odd ? 8 : 0);              // expert idx of cv[0]

    // ---- iterative top-8 over the 128 live candidates (per half)
    unsigned tpack0 = 0, tpack1 = 0;
    float tw[8];
    float wsum = 0.0f;
    #pragma unroll
    for (int k = 0; k < 8; k++) {
        float lm = fmaxf(fmaxf(fmaxf(cv[0], cv[1]), fmaxf(cv[2], cv[3])),
                         fmaxf(fmaxf(cv[4], cv[5]), fmaxf(cv[6], cv[7])));
        unsigned lmu  = f2ou(lm);
        unsigned winu = __reduce_max_sync(halfmask, lmu);
        unsigned bal  = __ballot_sync(halfmask, lmu == winu);  // bits at lane pos
        int wl = __ffs((int)bal) - 1;                   // global lane of winner
        bool amw = (lane == wl);
        float win = ou2f(winu);

        int slot = 0;
        #pragma unroll
        for (int i = 7; i >= 0; i--) if (cv[i] == win) slot = i;  // lowest match
        #pragma unroll
        for (int i = 0; i < 8; i++) if (amw && cv[i] == win) cv[i] = -3.0e38f;

        int myidx = ebase + slot;
        int bi = __shfl_sync(FULLM, myidx, wl);         // uniform per half

        float w = win - __ldg(bias + bi);               // sigmoid score (+-1 ulp)
        if (k < 4) tpack0 |= (unsigned)bi << (k * 8);
        else       tpack1 |= (unsigned)bi << ((k - 4) * 8);
        tw[k] = w;
        wsum += w;
    }

    float inv = 2.5f * __fdividef(1.0f, wsum + 1e-20f);

    if (hl == 0) {                                      // lanes 0 and 16 write
        long long base = (long long)token * 8;
        float4* oi4 = (float4*)(out_idx + base);
        float4* ow4 = (float4*)(out_w   + base);
        oi4[0] = make_float4((float)(tpack0 & 255), (float)((tpack0 >> 8) & 255),
                             (float)((tpack0 >> 16) & 255), (float)(tpack0 >> 24));
        oi4[1] = make_float4((float)(tpack1 & 255), (float)((tpack1 >> 8) & 255),
                             (float)((tpack1 >> 16) & 255), (float)(tpack1 >> 24));
        ow4[0] = make_float4(tw[0] * inv, tw[1] * inv, tw[2] * inv, tw[3] * inv);
        ow4[1] = make_float4(tw[4] * inv, tw[5] * inv, tw[6] * inv, tw[7] * inv);
    }
}

extern "C" void kernel_launch(void* const* d_in, const int* in_sizes, int n_in,
                              void* d_out, int out_size)
{
    const float* logits = (const float*)d_in[0];
    const float* bias   = (const float*)d_in[1];
    int T = in_sizes[0] / 256;

    float* out     = (float*)d_out;
    float* out_idx = out;
    float* out_w   = out + (long long)T * 8;

    const int WARPS_PER_BLOCK = 8;                      // 16 tokens per block
    int nwarps = (T + 1) / 2;
    dim3 block(WARPS_PER_BLOCK * 32);
    dim3 grid((nwarps + WARPS_PER_BLOCK - 1) / WARPS_PER_BLOCK);
    deepseek_router_kernel<<<grid, block>>>(logits, bias, out_idx, out_w, T);
}